// round 14
// baseline (speedup 1.0000x reference)
#include <cuda_runtime.h>
#include <cuda_fp16.h>
#include <cstdint>
#include <math.h>

#define NWIN 2048
#define TT   64
#define CC   256
#define MD   128
#define HID  1024
#define NTOK (NWIN*TT)   // 131072

// ---------------- scratch ----------------
__device__ __align__(16) __half g_xn[NTOK*CC];
__device__ __align__(16) __half g_qkv[NTOK*768];
__device__ __align__(16) __half g_ce[NTOK*MD];
__device__ __align__(16) __half g_att[NTOK*CC];
__device__ __align__(16) __half g_attce[NTOK*MD];
__device__ __align__(16) __half g_h[NTOK*HID];
__device__ __align__(16) __half g_h2[NTOK*HID];
__device__ __align__(16) __half g_Wqkv[768*256];    // [N][K]
__device__ __align__(16) float  g_bqkv[768];
__device__ __align__(16) __half g_Wp[256*256];      // [N][K]
__device__ __align__(16) __half g_Wm[128*128];
__device__ __align__(16) __half g_W1[1024*256];
__device__ __align__(16) __half g_W2[256*1024];

__device__ __forceinline__ int win2glob(int row){
    int w = row >> 6, t = row & 63;
    int b = w >> 8, wi = w & 255;
    int gy = ((wi >> 4) << 3) + (t >> 3);
    int gx = ((wi & 15) << 3) + (t & 7);
    return (b*128 + gy)*128 + gx;
}

__device__ __forceinline__ void mma_f16(float* c, const uint32_t* a, const uint32_t* b){
    asm volatile("mma.sync.aligned.m16n8k16.row.col.f32.f16.f16.f32 "
        "{%0,%1,%2,%3}, {%4,%5,%6,%7}, {%8,%9}, {%0,%1,%2,%3};"
        : "+f"(c[0]), "+f"(c[1]), "+f"(c[2]), "+f"(c[3])
        : "r"(a[0]), "r"(a[1]), "r"(a[2]), "r"(a[3]), "r"(b[0]), "r"(b[1]));
}
__device__ __forceinline__ uint32_t smem_u32(const void* p){
    uint32_t a;
    asm("{ .reg .u64 t; cvta.to.shared.u64 t, %1; cvt.u32.u64 %0, t; }" : "=r"(a) : "l"(p));
    return a;
}
__device__ __forceinline__ void cpasync16(uint32_t dst, const void* src){
    asm volatile("cp.async.ca.shared.global [%0], [%1], 16;" :: "r"(dst), "l"(src));
}
#define CP_COMMIT() asm volatile("cp.async.commit_group;" ::: "memory")
__device__ __forceinline__ uint32_t f2h2(float a, float b){
    __half2 h = __floats2half2_rn(a, b);
    return *(uint32_t*)&h;
}

// ---------------- weight prep: transpose+fp16 ----------------
__global__ void prep_wqkv(const float* __restrict__ Wq, const float* __restrict__ bq,
                          const float* __restrict__ Wkv, const float* __restrict__ bkv){
    int i = blockIdx.x*blockDim.x + threadIdx.x;   // 768*256
    int n = i >> 8, k = i & 255;
    float v = (n < 256) ? Wq[k*256 + n] : Wkv[k*512 + (n - 256)];
    g_Wqkv[i] = __float2half_rn(v);
    if (i < 768) g_bqkv[i] = (i < 256) ? bq[i] : bkv[i - 256];
}
__global__ void transpose_h(const float* __restrict__ in, __half* __restrict__ out, int K, int N){
    int i = blockIdx.x*blockDim.x + threadIdx.x;   // N*K
    int n = i / K, k = i % K;
    out[i] = __float2half_rn(in[(size_t)k*N + n]);
}

// ---------------- LayerNorm (fp16 output) ----------------
template<bool GATHER>
__global__ void ln_kernel(const float* __restrict__ x, __half* __restrict__ out,
                          const float* __restrict__ gg, const float* __restrict__ bb){
    int row  = blockIdx.x*8 + (threadIdx.x >> 5);
    int lane = threadIdx.x & 31;
    const float* src = x + (size_t)(GATHER ? win2glob(row) : row)*CC;
    float v[8]; float s = 0.f;
    #pragma unroll
    for(int i=0;i<8;i++){ v[i] = src[lane + i*32]; s += v[i]; }
    #pragma unroll
    for(int o=16;o;o>>=1) s += __shfl_xor_sync(0xffffffffu, s, o);
    float mean = s * (1.f/CC);
    float s2 = 0.f;
    #pragma unroll
    for(int i=0;i<8;i++){ float d = v[i]-mean; s2 += d*d; }
    #pragma unroll
    for(int o=16;o;o>>=1) s2 += __shfl_xor_sync(0xffffffffu, s2, o);
    float rstd = rsqrtf(s2*(1.f/CC) + 1e-5f);
    __half* dst = out + (size_t)row*CC;
    #pragma unroll
    for(int i=0;i<8;i++){
        int c = lane + i*32;
        dst[c] = __float2half_rn((v[i]-mean)*rstd*gg[c] + bb[c]);
    }
}

// ---------------- coordinate embedding (fp16 out) ----------------
__global__ void ce_kernel(const float* __restrict__ cor, const float* __restrict__ Wce,
                          const float* __restrict__ bce){
    int i = blockIdx.x*blockDim.x + threadIdx.x;
    int row = i >> 7, m = i & 127;
    int gp = win2glob(row)*2;
    g_ce[i] = __float2half_rn(cor[gp]*Wce[m] + cor[gp+1]*Wce[MD+m] + bce[m]);
}

// ---------------- attention: tensor-core (FA2-style), fp16 in/out ----------------
#define QP 136
#define CP 72
#define ATT_SMEM ((3*64*QP + 64*CP)*2)
__global__ void __launch_bounds__(256) attn_kernel(){
    extern __shared__ __half sm_att[];
    __half* Qs = sm_att;             // [64][136]
    __half* Ks = Qs + 64*QP;
    __half* Vs = Ks + 64*QP;
    __half* Cs = Vs + 64*QP;         // [64][72]

    int blk = blockIdx.x;            // 4096
    int w = blk >> 1, hh = blk & 1;
    int pw = (w + 1024) & 2047;
    int tid = threadIdx.x;
    int wid = tid >> 5, lane = tid & 31;
    int ch = wid >> 1;               // local head 0..3
    int qh = wid & 1;                // query half
    int g = lane >> 2, tg = lane & 3;

    for(int i=tid; i<1024; i+=256){
        int r = i >> 4, seg = (i & 15) << 3;
        const __half* bq_ = g_qkv + (size_t)(w*64 + r)*768 + hh*128;
        const __half* bk_ = g_qkv + (size_t)(pw*64 + r)*768 + 256 + hh*128;
        const __half* bv_ = g_qkv + (size_t)(pw*64 + r)*768 + 512 + hh*128;
        *(int4*)&Qs[r*QP + seg] = *(const int4*)(bq_ + seg);
        *(int4*)&Ks[r*QP + seg] = *(const int4*)(bk_ + seg);
        *(int4*)&Vs[r*QP + seg] = *(const int4*)(bv_ + seg);
    }
    for(int i=tid; i<512; i+=256){
        int r = i >> 3, seg = (i & 7) << 3;
        *(int4*)&Cs[r*CP + seg] = *(const int4*)(g_ce + (size_t)(w*64 + r)*128 + hh*64 + seg);
    }
    __syncthreads();

    int c0 = ch*32;
    int lr = lane & 7;
    int ts4 = lane >> 3;
    int ts2 = ts4 & 1;

    uint32_t qf[2][2][4];
    #pragma unroll
    for(int mt=0; mt<2; mt++){
        #pragma unroll
        for(int kc=0; kc<2; kc++){
            int row = qh*32 + mt*16 + lr + ((ts4 & 1) << 3);
            int col = c0 + kc*16 + ((ts4 & 2) << 2);
            uint32_t addr = smem_u32(&Qs[row*QP + col]);
            asm volatile("ldmatrix.sync.aligned.m8n8.x4.shared.b16 {%0,%1,%2,%3}, [%4];"
                : "=r"(qf[mt][kc][0]), "=r"(qf[mt][kc][1]),
                  "=r"(qf[mt][kc][2]), "=r"(qf[mt][kc][3]) : "r"(addr));
        }
    }

    float S[2][8][4];
    #pragma unroll
    for(int mt=0;mt<2;mt++)
        #pragma unroll
        for(int nt=0;nt<8;nt++)
            #pragma unroll
            for(int i=0;i<4;i++) S[mt][nt][i] = 0.f;

    #pragma unroll
    for(int kc=0; kc<2; kc++){
        #pragma unroll
        for(int nt=0; nt<8; nt++){
            uint32_t bb[2];
            uint32_t addr = smem_u32(&Ks[(nt*8 + lr)*QP + c0 + kc*16 + ts2*8]);
            asm volatile("ldmatrix.sync.aligned.m8n8.x2.shared.b16 {%0,%1}, [%2];"
                : "=r"(bb[0]), "=r"(bb[1]) : "r"(addr));
            mma_f16(S[0][nt], qf[0][kc], bb);
            mma_f16(S[1][nt], qf[1][kc], bb);
        }
    }

    const float sc = 0.17677669529663687f;
    float inv[2][2];
    #pragma unroll
    for(int mt=0;mt<2;mt++){
        #pragma unroll
        for(int rh=0;rh<2;rh++){
            float m = -1e30f;
            #pragma unroll
            for(int nt=0;nt<8;nt++){
                m = fmaxf(m, S[mt][nt][rh*2]);
                m = fmaxf(m, S[mt][nt][rh*2+1]);
            }
            m = fmaxf(m, __shfl_xor_sync(0xffffffffu, m, 1));
            m = fmaxf(m, __shfl_xor_sync(0xffffffffu, m, 2));
            float sm_ = 0.f;
            #pragma unroll
            for(int nt=0;nt<8;nt++){
                float p0 = expf(sc*(S[mt][nt][rh*2]   - m));
                float p1 = expf(sc*(S[mt][nt][rh*2+1] - m));
                S[mt][nt][rh*2] = p0; S[mt][nt][rh*2+1] = p1;
                sm_ += p0 + p1;
            }
            sm_ += __shfl_xor_sync(0xffffffffu, sm_, 1);
            sm_ += __shfl_xor_sync(0xffffffffu, sm_, 2);
            inv[mt][rh] = 1.f/sm_;
        }
    }

    float AV[2][4][4], AC[2][2][4];
    #pragma unroll
    for(int mt=0;mt<2;mt++){
        #pragma unroll
        for(int dn=0;dn<4;dn++)
            #pragma unroll
            for(int i=0;i<4;i++) AV[mt][dn][i] = 0.f;
        #pragma unroll
        for(int dn=0;dn<2;dn++)
            #pragma unroll
            for(int i=0;i<4;i++) AC[mt][dn][i] = 0.f;
    }

    #pragma unroll
    for(int kc2=0; kc2<4; kc2++){
        uint32_t pf[2][4];
        #pragma unroll
        for(int mt=0;mt<2;mt++){
            pf[mt][0] = f2h2(S[mt][2*kc2][0],   S[mt][2*kc2][1]);
            pf[mt][1] = f2h2(S[mt][2*kc2][2],   S[mt][2*kc2][3]);
            pf[mt][2] = f2h2(S[mt][2*kc2+1][0], S[mt][2*kc2+1][1]);
            pf[mt][3] = f2h2(S[mt][2*kc2+1][2], S[mt][2*kc2+1][3]);
        }
        #pragma unroll
        for(int dn=0; dn<4; dn++){
            uint32_t bb[2];
            uint32_t addr = smem_u32(&Vs[(kc2*16 + ts2*8 + lr)*QP + c0 + dn*8]);
            asm volatile("ldmatrix.sync.aligned.m8n8.x2.trans.shared.b16 {%0,%1}, [%2];"
                : "=r"(bb[0]), "=r"(bb[1]) : "r"(addr));
            mma_f16(AV[0][dn], pf[0], bb);
            mma_f16(AV[1][dn], pf[1], bb);
        }
        #pragma unroll
        for(int dn=0; dn<2; dn++){
            uint32_t bb[2];
            uint32_t addr = smem_u32(&Cs[(kc2*16 + ts2*8 + lr)*CP + ch*16 + dn*8]);
            asm volatile("ldmatrix.sync.aligned.m8n8.x2.trans.shared.b16 {%0,%1}, [%2];"
                : "=r"(bb[0]), "=r"(bb[1]) : "r"(addr));
            mma_f16(AC[0][dn], pf[0], bb);
            mma_f16(AC[1][dn], pf[1], bb);
        }
    }

    #pragma unroll
    for(int mt=0;mt<2;mt++){
        #pragma unroll
        for(int rh=0;rh<2;rh++){
            int lrow = qh*32 + mt*16 + g + rh*8;
            int grow = w*64 + lrow;
            float iv = inv[mt][rh];
            __half* ao = g_att + (size_t)grow*256 + hh*128 + c0;
            #pragma unroll
            for(int dn=0;dn<4;dn++)
                *(__half2*)(ao + dn*8 + 2*tg) =
                    __floats2half2_rn(AV[mt][dn][rh*2]*iv, AV[mt][dn][rh*2+1]*iv);
            __half* co = g_attce + (size_t)grow*128 + hh*64 + ch*16;
            #pragma unroll
            for(int dn=0;dn<2;dn++){
                __half2 cv = *(__half2*)&Cs[lrow*CP + ch*16 + dn*8 + 2*tg];
                float2 cf = __half22float2(cv);
                *(__half2*)(co + dn*8 + 2*tg) =
                    __floats2half2_rn(AC[mt][dn][rh*2]*iv - cf.x,
                                      AC[mt][dn][rh*2+1]*iv - cf.y);
            }
        }
    }
}

// ---------------- FP16 mma.sync GEMM: 128x128 block, chunk K=64, 3-stage, 2 CTAs/SM ----------------
// MODE 0: store fp32; 1: scatter+residual(half)->fp32; 2: scatter fp32;
// MODE 3: fp32 out += val; 4: store fp16
#define KCH 64
#define PITCHH 72
#define AS_H (128*PITCHH)
#define ST_H (2*AS_H)
#define NSTAGE 3

template<int MODE>
__global__ void __launch_bounds__(256, 2) gemm_mma(const __half* __restrict__ A,
        const __half* __restrict__ Wt, const float* __restrict__ bias,
        void* __restrict__ outv, int K, int Ntot, const __half* __restrict__ add){
    extern __shared__ __half smh[];

    int tid = threadIdx.x;
    int wid = tid >> 5, lane = tid & 31;
    int g = lane >> 2, tg = lane & 3;
    int bm = blockIdx.y << 7, bn = blockIdx.x << 7;
    int mBase = (wid & 3) << 5;
    int nBase = (wid >> 2) << 6;

    float c[2][8][4];
    #pragma unroll
    for(int i=0;i<2;i++)
        #pragma unroll
        for(int j=0;j<8;j++)
            #pragma unroll
            for(int q=0;q<4;q++) c[i][j][q] = 0.f;

    int nch = K / KCH;
    uint32_t smB = smem_u32(smh);

    auto issue = [&](int ch){
        uint32_t st = smB + (uint32_t)((ch % NSTAGE) * ST_H) * 2u;
        int k0 = ch * KCH;
        #pragma unroll
        for(int i=0;i<4;i++){
            int idx = i*256 + tid;
            int row = idx >> 3, seg = (idx & 7) << 3;
            cpasync16(st + (uint32_t)(row*PITCHH + seg)*2u,
                      A + (size_t)(bm + row)*K + k0 + seg);
            cpasync16(st + (uint32_t)(AS_H + row*PITCHH + seg)*2u,
                      Wt + (size_t)(bn + row)*K + k0 + seg);
        }
        CP_COMMIT();
    };

    issue(0);
    if (nch > 1) issue(1); else CP_COMMIT();

    for(int ch=0; ch<nch; ch++){
        asm volatile("cp.async.wait_group 1;" ::: "memory");
        __syncthreads();
        if (ch + 2 < nch) issue(ch + 2);
        else CP_COMMIT();

        const uint32_t* Au = (const uint32_t*)(smh + (size_t)(ch % NSTAGE) * ST_H);
        const uint32_t* Bu = Au + AS_H/2;

        uint32_t afA[2][4], bfA[8][2], afB[2][4], bfB[8][2];

        #define LOAD_FRAGS(kk, af, bf) do{                               \
            int kc = (kk) >> 1;                                          \
            _Pragma("unroll")                                            \
            for(int mt=0; mt<2; mt++){                                   \
                int r0 = mBase + (mt<<4) + g;                            \
                af[mt][0] = Au[ r0   *(PITCHH/2) + kc + tg    ];         \
                af[mt][1] = Au[(r0+8)*(PITCHH/2) + kc + tg    ];         \
                af[mt][2] = Au[ r0   *(PITCHH/2) + kc + tg + 4];         \
                af[mt][3] = Au[(r0+8)*(PITCHH/2) + kc + tg + 4];         \
            }                                                            \
            _Pragma("unroll")                                            \
            for(int j=0; j<8; j++){                                      \
                int n_ = nBase + (j<<3) + g;                             \
                bf[j][0] = Bu[n_*(PITCHH/2) + kc + tg    ];              \
                bf[j][1] = Bu[n_*(PITCHH/2) + kc + tg + 4];              \
            } }while(0)

        #define DO_MMA(af, bf) do{                                       \
            _Pragma("unroll")                                            \
            for(int mt=0; mt<2; mt++)                                    \
                _Pragma("unroll")                                        \
                for(int j=0; j<8; j++)                                   \
                    mma_f16(c[mt][j], af[mt], bf[j]);                    \
            }while(0)

        LOAD_FRAGS(0, afA, bfA);
        LOAD_FRAGS(16, afB, bfB);  DO_MMA(afA, bfA);
        LOAD_FRAGS(32, afA, bfA);  DO_MMA(afB, bfB);
        LOAD_FRAGS(48, afB, bfB);  DO_MMA(afA, bfA);
        DO_MMA(afB, bfB);

        #undef LOAD_FRAGS
        #undef DO_MMA
    }

    float* outf = (float*)outv;
    __half* outh = (__half*)outv;
    #pragma unroll
    for(int mt=0; mt<2; mt++){
        #pragma unroll
        for(int half=0; half<2; half++){
            int grow = bm + mBase + (mt<<4) + g + (half<<3);
            int orow = (MODE==1 || MODE==2) ? win2glob(grow) : grow;
            #pragma unroll
            for(int j=0; j<8; j++){
                int cn = bn + nBase + (j<<3) + (tg<<1);
                float2 bb = *(const float2*)(bias + cn);
                float v0 = c[mt][j][half*2+0] + bb.x;
                float v1 = c[mt][j][half*2+1] + bb.y;
                if (MODE == 0){
                    *(float2*)(outf + (size_t)grow*Ntot + cn) = make_float2(v0, v1);
                } else if (MODE == 1){
                    __half2 ad = *(const __half2*)(add + (size_t)grow*Ntot + cn);
                    *(float2*)(outf + (size_t)orow*Ntot + cn) =
                        make_float2(v0 + __half2float(ad.x), v1 + __half2float(ad.y));
                } else if (MODE == 2){
                    *(float2*)(outf + (size_t)orow*Ntot + cn) = make_float2(v0, v1);
                } else if (MODE == 3){
                    float2 o = *(float2*)(outf + (size_t)grow*Ntot + cn);
                    *(float2*)(outf + (size_t)grow*Ntot + cn) = make_float2(o.x+v0, o.y+v1);
                } else {
                    *(__half2*)(outh + (size_t)grow*Ntot + cn) = __floats2half2_rn(v0, v1);
                }
            }
        }
    }
}
#define GEMM_SMEM (NSTAGE*ST_H*2)

// ---------------- depthwise 3x3 conv + GELU: smem-tiled ----------------
#define DW_SMEM (6*128*64*2)
__global__ void __launch_bounds__(256) dwconv_gelu(const float* __restrict__ Wdw,
                                                   const float* __restrict__ bdw){
    extern __shared__ __half sh[];
    int blk = blockIdx.x;
    int cg = blk & 15, yt = (blk >> 4) & 31, b = blk >> 9;
    int y0 = yt << 2, c0 = cg << 6;
    int tid = threadIdx.x;

    #pragma unroll
    for(int i = tid; i < 6144; i += 256){
        int r = i >> 10;
        int rem = i & 1023;
        int xx = rem >> 3, seg = (rem & 7) << 3;
        int yy = y0 - 1 + r;
        int4 val = make_int4(0,0,0,0);
        if (yy >= 0 && yy < 128)
            val = *(const int4*)(g_h + ((size_t)((b*128+yy)*128 + xx))*1024 + c0 + seg);
        *(int4*)(sh + ((r*128 + xx) << 6) + seg) = val;
    }
    __syncthreads();

    int ch2 = tid & 31;
    int xs = tid >> 5;
    float wl[9], wh[9];
    #pragma unroll
    for(int t2=0;t2<9;t2++){
        wl[t2] = Wdw[t2*1024 + c0 + 2*ch2];
        wh[t2] = Wdw[t2*1024 + c0 + 2*ch2 + 1];
    }
    float bl = bdw[c0 + 2*ch2], bh = bdw[c0 + 2*ch2 + 1];

    #pragma unroll
    for(int r=0;r<4;r++){
        #pragma unroll
        for(int xi=0;xi<16;xi++){
            int x = xs + (xi << 3);
            float al = bl, ah = bh;
            #pragma unroll
            for(int ky=0;ky<3;ky++){
                int sr = r + ky;
                #pragma unroll
                for(int kx=0;kx<3;kx++){
                    int xx = x + kx - 1;
                    if (xx >= 0 && xx < 128){
                        __half2 hv = *(const __half2*)(sh + ((sr*128 + xx) << 6) + 2*ch2);
                        float2 f = __half22float2(hv);
                        al = fmaf(f.x, wl[ky*3+kx], al);
                        ah = fmaf(f.y, wh[ky*3+kx], ah);
                    }
                }
            }
            float gl = 0.5f*al*(1.f + erff(al*0.70710678118654752f));
            float gh = 0.5f*ah*(1.f + erff(ah*0.70710678118654752f));
            *(__half2*)(g_h2 + ((size_t)((b*128 + y0 + r)*128 + x))*1024 + c0 + 2*ch2)
                = __floats2half2_rn(gl, gh);
        }
    }
}

// ---------------- launch ----------------
extern "C" void kernel_launch(void* const* d_in, const int* in_sizes, int n_in,
                              void* d_out, int out_size){
    const float* x     = (const float*)d_in[0];
    const float* cor   = (const float*)d_in[1];
    const float* g1    = (const float*)d_in[2];
    const float* b1    = (const float*)d_in[3];
    const float* Wq    = (const float*)d_in[4];
    const float* bq    = (const float*)d_in[5];
    const float* Wkv   = (const float*)d_in[6];
    const float* bkv   = (const float*)d_in[7];
    const float* Wproj = (const float*)d_in[8];
    const float* bproj = (const float*)d_in[9];
    const float* Wce   = (const float*)d_in[10];
    const float* bce   = (const float*)d_in[11];
    const float* Wmp   = (const float*)d_in[12];
    const float* bmp   = (const float*)d_in[13];
    const float* g2    = (const float*)d_in[14];
    const float* b2    = (const float*)d_in[15];
    const float* Wfc1  = (const float*)d_in[16];
    const float* bfc1  = (const float*)d_in[17];
    const float* Wdw   = (const float*)d_in[18];
    const float* bdw   = (const float*)d_in[19];
    const float* Wfc2  = (const float*)d_in[20];
    const float* bfc2  = (const float*)d_in[21];

    float* out  = (float*)d_out;
    float* xout = out;
    float* mout = out + (size_t)NTOK*CC;

    __half *p_xn, *p_qkv, *p_att, *p_attce, *p_h, *p_h2, *p_Wqkv, *p_Wp, *p_Wm, *p_W1, *p_W2;
    float *p_bqkv;
    cudaGetSymbolAddress((void**)&p_xn,    g_xn);
    cudaGetSymbolAddress((void**)&p_qkv,   g_qkv);
    cudaGetSymbolAddress((void**)&p_att,   g_att);
    cudaGetSymbolAddress((void**)&p_attce, g_attce);
    cudaGetSymbolAddress((void**)&p_h,     g_h);
    cudaGetSymbolAddress((void**)&p_h2,    g_h2);
    cudaGetSymbolAddress((void**)&p_Wqkv,  g_Wqkv);
    cudaGetSymbolAddress((void**)&p_bqkv,  g_bqkv);
    cudaGetSymbolAddress((void**)&p_Wp,    g_Wp);
    cudaGetSymbolAddress((void**)&p_Wm,    g_Wm);
    cudaGetSymbolAddress((void**)&p_W1,    g_W1);
    cudaGetSymbolAddress((void**)&p_W2,    g_W2);

    cudaFuncSetAttribute(gemm_mma<1>, cudaFuncAttributeMaxDynamicSharedMemorySize, GEMM_SMEM);
    cudaFuncSetAttribute(gemm_mma<2>, cudaFuncAttributeMaxDynamicSharedMemorySize, GEMM_SMEM);
    cudaFuncSetAttribute(gemm_mma<3>, cudaFuncAttributeMaxDynamicSharedMemorySize, GEMM_SMEM);
    cudaFuncSetAttribute(gemm_mma<4>, cudaFuncAttributeMaxDynamicSharedMemorySize, GEMM_SMEM);
    cudaFuncSetAttribute(dwconv_gelu, cudaFuncAttributeMaxDynamicSharedMemorySize, DW_SMEM);
    cudaFuncSetAttribute(attn_kernel, cudaFuncAttributeMaxDynamicSharedMemorySize, ATT_SMEM);

    prep_wqkv<<<768, 256>>>(Wq, bq, Wkv, bkv);
    transpose_h<<<256, 256>>>(Wproj, p_Wp, 256, 256);
    transpose_h<<<64, 256>>>(Wmp, p_Wm, 128, 128);
    transpose_h<<<1024, 256>>>(Wfc1, p_W1, 256, 1024);
    transpose_h<<<1024, 256>>>(Wfc2, p_W2, 1024, 256);

    ln_kernel<true><<<NTOK/8, 256>>>(x, p_xn, g1, b1);
    ce_kernel<<<(NTOK*MD)/256, 256>>>(cor, Wce, bce);
    gemm_mma<4><<<dim3(6, 1024), 256, GEMM_SMEM>>>(p_xn, p_Wqkv, p_bqkv, p_qkv, 256, 768, nullptr);
    attn_kernel<<<NWIN*2, 256, ATT_SMEM>>>();
    gemm_mma<1><<<dim3(2, 1024), 256, GEMM_SMEM>>>(p_att, p_Wp, bproj, xout, 256, 256, p_xn);
    gemm_mma<2><<<dim3(1, 1024), 256, GEMM_SMEM>>>(p_attce, p_Wm, bmp, mout, 128, 128, nullptr);
    ln_kernel<false><<<NTOK/8, 256>>>(xout, p_att, g2, b2);
    gemm_mma<4><<<dim3(8, 1024), 256, GEMM_SMEM>>>(p_att, p_W1, bfc1, p_h, 256, 1024, nullptr);
    dwconv_gelu<<<4096, 256, DW_SMEM>>>(Wdw, bdw);
    gemm_mma<3><<<dim3(2, 1024), 256, GEMM_SMEM>>>(p_h2, p_W2, bfc2, xout, 1024, 256, nullptr);
}

// round 16
// speedup vs baseline: 1.0058x; 1.0058x over previous
#include <cuda_runtime.h>
#include <cuda_fp16.h>
#include <cstdint>
#include <math.h>

#define NWIN 2048
#define TT   64
#define CC   256
#define MD   128
#define HID  1024
#define NTOK (NWIN*TT)   // 131072

// ---------------- scratch ----------------
__device__ __align__(16) __half g_xn[NTOK*CC];
__device__ __align__(16) __half g_qkv[NTOK*768];
__device__ __align__(16) __half g_ce[NTOK*MD];
__device__ __align__(16) __half g_att[NTOK*CC];
__device__ __align__(16) __half g_attce[NTOK*MD];
__device__ __align__(16) __half g_h[NTOK*HID];
__device__ __align__(16) __half g_h2[NTOK*HID];
__device__ __align__(16) __half g_Wqkv[768*256];    // [N][K]
__device__ __align__(16) float  g_bqkv[768];
__device__ __align__(16) __half g_Wp[256*256];      // [N][K]
__device__ __align__(16) __half g_Wm[128*128];
__device__ __align__(16) __half g_W1[1024*256];
__device__ __align__(16) __half g_W2[256*1024];

__device__ __forceinline__ int win2glob(int row){
    int w = row >> 6, t = row & 63;
    int b = w >> 8, wi = w & 255;
    int gy = ((wi >> 4) << 3) + (t >> 3);
    int gx = ((wi & 15) << 3) + (t & 7);
    return (b*128 + gy)*128 + gx;
}

__device__ __forceinline__ void mma_f16(float* c, const uint32_t* a, const uint32_t* b){
    asm volatile("mma.sync.aligned.m16n8k16.row.col.f32.f16.f16.f32 "
        "{%0,%1,%2,%3}, {%4,%5,%6,%7}, {%8,%9}, {%0,%1,%2,%3};"
        : "+f"(c[0]), "+f"(c[1]), "+f"(c[2]), "+f"(c[3])
        : "r"(a[0]), "r"(a[1]), "r"(a[2]), "r"(a[3]), "r"(b[0]), "r"(b[1]));
}
__device__ __forceinline__ uint32_t smem_u32(const void* p){
    uint32_t a;
    asm("{ .reg .u64 t; cvta.to.shared.u64 t, %1; cvt.u32.u64 %0, t; }" : "=r"(a) : "l"(p));
    return a;
}
__device__ __forceinline__ void cpasync16(uint32_t dst, const void* src){
    asm volatile("cp.async.cg.shared.global [%0], [%1], 16;" :: "r"(dst), "l"(src));
}
#define CP_COMMIT() asm volatile("cp.async.commit_group;" ::: "memory")
__device__ __forceinline__ uint32_t f2h2(float a, float b){
    __half2 h = __floats2half2_rn(a, b);
    return *(uint32_t*)&h;
}

// ---------------- weight prep: transpose+fp16 ----------------
__global__ void prep_wqkv(const float* __restrict__ Wq, const float* __restrict__ bq,
                          const float* __restrict__ Wkv, const float* __restrict__ bkv){
    int i = blockIdx.x*blockDim.x + threadIdx.x;   // 768*256
    int n = i >> 8, k = i & 255;
    float v = (n < 256) ? Wq[k*256 + n] : Wkv[k*512 + (n - 256)];
    g_Wqkv[i] = __float2half_rn(v);
    if (i < 768) g_bqkv[i] = (i < 256) ? bq[i] : bkv[i - 256];
}
__global__ void transpose_h(const float* __restrict__ in, __half* __restrict__ out, int K, int N){
    int i = blockIdx.x*blockDim.x + threadIdx.x;   // N*K
    int n = i / K, k = i % K;
    out[i] = __float2half_rn(in[(size_t)k*N + n]);
}

// ---------------- LayerNorm (fp16 output) ----------------
template<bool GATHER>
__global__ void ln_kernel(const float* __restrict__ x, __half* __restrict__ out,
                          const float* __restrict__ gg, const float* __restrict__ bb){
    int row  = blockIdx.x*8 + (threadIdx.x >> 5);
    int lane = threadIdx.x & 31;
    const float* src = x + (size_t)(GATHER ? win2glob(row) : row)*CC;
    float v[8]; float s = 0.f;
    #pragma unroll
    for(int i=0;i<8;i++){ v[i] = src[lane + i*32]; s += v[i]; }
    #pragma unroll
    for(int o=16;o;o>>=1) s += __shfl_xor_sync(0xffffffffu, s, o);
    float mean = s * (1.f/CC);
    float s2 = 0.f;
    #pragma unroll
    for(int i=0;i<8;i++){ float d = v[i]-mean; s2 += d*d; }
    #pragma unroll
    for(int o=16;o;o>>=1) s2 += __shfl_xor_sync(0xffffffffu, s2, o);
    float rstd = rsqrtf(s2*(1.f/CC) + 1e-5f);
    __half* dst = out + (size_t)row*CC;
    #pragma unroll
    for(int i=0;i<8;i++){
        int c = lane + i*32;
        dst[c] = __float2half_rn((v[i]-mean)*rstd*gg[c] + bb[c]);
    }
}

// ---------------- coordinate embedding (fp16 out) ----------------
__global__ void ce_kernel(const float* __restrict__ cor, const float* __restrict__ Wce,
                          const float* __restrict__ bce){
    int i = blockIdx.x*blockDim.x + threadIdx.x;
    int row = i >> 7, m = i & 127;
    int gp = win2glob(row)*2;
    g_ce[i] = __float2half_rn(cor[gp]*Wce[m] + cor[gp+1]*Wce[MD+m] + bce[m]);
}

// ---------------- attention: tensor-core (FA2-style), fp16 in/out ----------------
#define QP 136
#define CP 72
#define ATT_SMEM ((3*64*QP + 64*CP)*2)
__global__ void __launch_bounds__(256) attn_kernel(){
    extern __shared__ __half sm_att[];
    __half* Qs = sm_att;             // [64][136]
    __half* Ks = Qs + 64*QP;
    __half* Vs = Ks + 64*QP;
    __half* Cs = Vs + 64*QP;         // [64][72]

    int blk = blockIdx.x;            // 4096
    int w = blk >> 1, hh = blk & 1;
    int pw = (w + 1024) & 2047;
    int tid = threadIdx.x;
    int wid = tid >> 5, lane = tid & 31;
    int ch = wid >> 1;               // local head 0..3
    int qh = wid & 1;                // query half
    int g = lane >> 2, tg = lane & 3;

    for(int i=tid; i<1024; i+=256){
        int r = i >> 4, seg = (i & 15) << 3;
        const __half* bq_ = g_qkv + (size_t)(w*64 + r)*768 + hh*128;
        const __half* bk_ = g_qkv + (size_t)(pw*64 + r)*768 + 256 + hh*128;
        const __half* bv_ = g_qkv + (size_t)(pw*64 + r)*768 + 512 + hh*128;
        *(int4*)&Qs[r*QP + seg] = *(const int4*)(bq_ + seg);
        *(int4*)&Ks[r*QP + seg] = *(const int4*)(bk_ + seg);
        *(int4*)&Vs[r*QP + seg] = *(const int4*)(bv_ + seg);
    }
    for(int i=tid; i<512; i+=256){
        int r = i >> 3, seg = (i & 7) << 3;
        *(int4*)&Cs[r*CP + seg] = *(const int4*)(g_ce + (size_t)(w*64 + r)*128 + hh*64 + seg);
    }
    __syncthreads();

    int c0 = ch*32;
    int lr = lane & 7;
    int ts4 = lane >> 3;
    int ts2 = ts4 & 1;

    uint32_t qf[2][2][4];
    #pragma unroll
    for(int mt=0; mt<2; mt++){
        #pragma unroll
        for(int kc=0; kc<2; kc++){
            int row = qh*32 + mt*16 + lr + ((ts4 & 1) << 3);
            int col = c0 + kc*16 + ((ts4 & 2) << 2);
            uint32_t addr = smem_u32(&Qs[row*QP + col]);
            asm volatile("ldmatrix.sync.aligned.m8n8.x4.shared.b16 {%0,%1,%2,%3}, [%4];"
                : "=r"(qf[mt][kc][0]), "=r"(qf[mt][kc][1]),
                  "=r"(qf[mt][kc][2]), "=r"(qf[mt][kc][3]) : "r"(addr));
        }
    }

    float S[2][8][4];
    #pragma unroll
    for(int mt=0;mt<2;mt++)
        #pragma unroll
        for(int nt=0;nt<8;nt++)
            #pragma unroll
            for(int i=0;i<4;i++) S[mt][nt][i] = 0.f;

    #pragma unroll
    for(int kc=0; kc<2; kc++){
        #pragma unroll
        for(int nt=0; nt<8; nt++){
            uint32_t bb[2];
            uint32_t addr = smem_u32(&Ks[(nt*8 + lr)*QP + c0 + kc*16 + ts2*8]);
            asm volatile("ldmatrix.sync.aligned.m8n8.x2.shared.b16 {%0,%1}, [%2];"
                : "=r"(bb[0]), "=r"(bb[1]) : "r"(addr));
            mma_f16(S[0][nt], qf[0][kc], bb);
            mma_f16(S[1][nt], qf[1][kc], bb);
        }
    }

    const float sc = 0.17677669529663687f;
    float inv[2][2];
    #pragma unroll
    for(int mt=0;mt<2;mt++){
        #pragma unroll
        for(int rh=0;rh<2;rh++){
            float m = -1e30f;
            #pragma unroll
            for(int nt=0;nt<8;nt++){
                m = fmaxf(m, S[mt][nt][rh*2]);
                m = fmaxf(m, S[mt][nt][rh*2+1]);
            }
            m = fmaxf(m, __shfl_xor_sync(0xffffffffu, m, 1));
            m = fmaxf(m, __shfl_xor_sync(0xffffffffu, m, 2));
            float sm_ = 0.f;
            #pragma unroll
            for(int nt=0;nt<8;nt++){
                float p0 = expf(sc*(S[mt][nt][rh*2]   - m));
                float p1 = expf(sc*(S[mt][nt][rh*2+1] - m));
                S[mt][nt][rh*2] = p0; S[mt][nt][rh*2+1] = p1;
                sm_ += p0 + p1;
            }
            sm_ += __shfl_xor_sync(0xffffffffu, sm_, 1);
            sm_ += __shfl_xor_sync(0xffffffffu, sm_, 2);
            inv[mt][rh] = 1.f/sm_;
        }
    }

    float AV[2][4][4], AC[2][2][4];
    #pragma unroll
    for(int mt=0;mt<2;mt++){
        #pragma unroll
        for(int dn=0;dn<4;dn++)
            #pragma unroll
            for(int i=0;i<4;i++) AV[mt][dn][i] = 0.f;
        #pragma unroll
        for(int dn=0;dn<2;dn++)
            #pragma unroll
            for(int i=0;i<4;i++) AC[mt][dn][i] = 0.f;
    }

    #pragma unroll
    for(int kc2=0; kc2<4; kc2++){
        uint32_t pf[2][4];
        #pragma unroll
        for(int mt=0;mt<2;mt++){
            pf[mt][0] = f2h2(S[mt][2*kc2][0],   S[mt][2*kc2][1]);
            pf[mt][1] = f2h2(S[mt][2*kc2][2],   S[mt][2*kc2][3]);
            pf[mt][2] = f2h2(S[mt][2*kc2+1][0], S[mt][2*kc2+1][1]);
            pf[mt][3] = f2h2(S[mt][2*kc2+1][2], S[mt][2*kc2+1][3]);
        }
        #pragma unroll
        for(int dn=0; dn<4; dn++){
            uint32_t bb[2];
            uint32_t addr = smem_u32(&Vs[(kc2*16 + ts2*8 + lr)*QP + c0 + dn*8]);
            asm volatile("ldmatrix.sync.aligned.m8n8.x2.trans.shared.b16 {%0,%1}, [%2];"
                : "=r"(bb[0]), "=r"(bb[1]) : "r"(addr));
            mma_f16(AV[0][dn], pf[0], bb);
            mma_f16(AV[1][dn], pf[1], bb);
        }
        #pragma unroll
        for(int dn=0; dn<2; dn++){
            uint32_t bb[2];
            uint32_t addr = smem_u32(&Cs[(kc2*16 + ts2*8 + lr)*CP + ch*16 + dn*8]);
            asm volatile("ldmatrix.sync.aligned.m8n8.x2.trans.shared.b16 {%0,%1}, [%2];"
                : "=r"(bb[0]), "=r"(bb[1]) : "r"(addr));
            mma_f16(AC[0][dn], pf[0], bb);
            mma_f16(AC[1][dn], pf[1], bb);
        }
    }

    #pragma unroll
    for(int mt=0;mt<2;mt++){
        #pragma unroll
        for(int rh=0;rh<2;rh++){
            int lrow = qh*32 + mt*16 + g + rh*8;
            int grow = w*64 + lrow;
            float iv = inv[mt][rh];
            __half* ao = g_att + (size_t)grow*256 + hh*128 + c0;
            #pragma unroll
            for(int dn=0;dn<4;dn++)
                *(__half2*)(ao + dn*8 + 2*tg) =
                    __floats2half2_rn(AV[mt][dn][rh*2]*iv, AV[mt][dn][rh*2+1]*iv);
            __half* co = g_attce + (size_t)grow*128 + hh*64 + ch*16;
            #pragma unroll
            for(int dn=0;dn<2;dn++){
                __half2 cv = *(__half2*)&Cs[lrow*CP + ch*16 + dn*8 + 2*tg];
                float2 cf = __half22float2(cv);
                *(__half2*)(co + dn*8 + 2*tg) =
                    __floats2half2_rn(AC[mt][dn][rh*2]*iv - cf.x,
                                      AC[mt][dn][rh*2+1]*iv - cf.y);
            }
        }
    }
}

// ---------------- FP16 mma.sync GEMM: 128x128 block, chunk K=64, 4-stage ----------------
// MODE 0: store fp32; 1: scatter+residual(half)->fp32; 2: scatter fp32;
// MODE 3: fp32 out += val; 4: store fp16
#define KCH 64
#define PITCHH 72
#define AS_H (128*PITCHH)
#define ST_H (2*AS_H)
#define NSTAGE 4

template<int MODE>
__global__ void __launch_bounds__(256) gemm_mma(const __half* __restrict__ A,
        const __half* __restrict__ Wt, const float* __restrict__ bias,
        void* __restrict__ outv, int K, int Ntot, const __half* __restrict__ add){
    extern __shared__ __half smh[];

    int tid = threadIdx.x;
    int wid = tid >> 5, lane = tid & 31;
    int g = lane >> 2, tg = lane & 3;
    int bm = blockIdx.y << 7, bn = blockIdx.x << 7;
    int mBase = (wid & 3) << 5;
    int nBase = (wid >> 2) << 6;

    float c[2][8][4];
    #pragma unroll
    for(int i=0;i<2;i++)
        #pragma unroll
        for(int j=0;j<8;j++)
            #pragma unroll
            for(int q=0;q<4;q++) c[i][j][q] = 0.f;

    int nch = K / KCH;
    uint32_t smB = smem_u32(smh);

    auto issue = [&](int ch){
        uint32_t st = smB + (uint32_t)((ch % NSTAGE) * ST_H) * 2u;
        int k0 = ch * KCH;
        #pragma unroll
        for(int i=0;i<4;i++){
            int idx = i*256 + tid;
            int row = idx >> 3, seg = (idx & 7) << 3;
            cpasync16(st + (uint32_t)(row*PITCHH + seg)*2u,
                      A + (size_t)(bm + row)*K + k0 + seg);
            cpasync16(st + (uint32_t)(AS_H + row*PITCHH + seg)*2u,
                      Wt + (size_t)(bn + row)*K + k0 + seg);
        }
        CP_COMMIT();
    };

    issue(0);
    if (nch > 1) issue(1); else CP_COMMIT();
    if (nch > 2) issue(2); else CP_COMMIT();

    for(int ch=0; ch<nch; ch++){
        asm volatile("cp.async.wait_group 2;" ::: "memory");
        __syncthreads();
        if (ch + 3 < nch) issue(ch + 3);
        else CP_COMMIT();

        const uint32_t* Au = (const uint32_t*)(smh + (size_t)(ch % NSTAGE) * ST_H);
        const uint32_t* Bu = Au + AS_H/2;

        uint32_t afA[2][4], bfA[8][2], afB[2][4], bfB[8][2];

        #define LOAD_FRAGS(kk, af, bf) do{                               \
            int kc = (kk) >> 1;                                          \
            _Pragma("unroll")                                            \
            for(int mt=0; mt<2; mt++){                                   \
                int r0 = mBase + (mt<<4) + g;                            \
                af[mt][0] = Au[ r0   *(PITCHH/2) + kc + tg    ];         \
                af[mt][1] = Au[(r0+8)*(PITCHH/2) + kc + tg    ];         \
                af[mt][2] = Au[ r0   *(PITCHH/2) + kc + tg + 4];         \
                af[mt][3] = Au[(r0+8)*(PITCHH/2) + kc + tg + 4];         \
            }                                                            \
            _Pragma("unroll")                                            \
            for(int j=0; j<8; j++){                                      \
                int n_ = nBase + (j<<3) + g;                             \
                bf[j][0] = Bu[n_*(PITCHH/2) + kc + tg    ];              \
                bf[j][1] = Bu[n_*(PITCHH/2) + kc + tg + 4];              \
            } }while(0)

        #define DO_MMA(af, bf) do{                                       \
            _Pragma("unroll")                                            \
            for(int mt=0; mt<2; mt++)                                    \
                _Pragma("unroll")                                        \
                for(int j=0; j<8; j++)                                   \
                    mma_f16(c[mt][j], af[mt], bf[j]);                    \
            }while(0)

        LOAD_FRAGS(0, afA, bfA);
        LOAD_FRAGS(16, afB, bfB);  DO_MMA(afA, bfA);
        LOAD_FRAGS(32, afA, bfA);  DO_MMA(afB, bfB);
        LOAD_FRAGS(48, afB, bfB);  DO_MMA(afA, bfA);
        DO_MMA(afB, bfB);

        #undef LOAD_FRAGS
        #undef DO_MMA
    }

    float* outf = (float*)outv;
    __half* outh = (__half*)outv;
    #pragma unroll
    for(int mt=0; mt<2; mt++){
        #pragma unroll
        for(int half=0; half<2; half++){
            int grow = bm + mBase + (mt<<4) + g + (half<<3);
            int orow = (MODE==1 || MODE==2) ? win2glob(grow) : grow;
            #pragma unroll
            for(int j=0; j<8; j++){
                int cn = bn + nBase + (j<<3) + (tg<<1);
                float2 bb = *(const float2*)(bias + cn);
                float v0 = c[mt][j][half*2+0] + bb.x;
                float v1 = c[mt][j][half*2+1] + bb.y;
                if (MODE == 0){
                    *(float2*)(outf + (size_t)grow*Ntot + cn) = make_float2(v0, v1);
                } else if (MODE == 1){
                    __half2 ad = *(const __half2*)(add + (size_t)grow*Ntot + cn);
                    *(float2*)(outf + (size_t)orow*Ntot + cn) =
                        make_float2(v0 + __half2float(ad.x), v1 + __half2float(ad.y));
                } else if (MODE == 2){
                    *(float2*)(outf + (size_t)orow*Ntot + cn) = make_float2(v0, v1);
                } else if (MODE == 3){
                    float2 o = *(float2*)(outf + (size_t)grow*Ntot + cn);
                    *(float2*)(outf + (size_t)grow*Ntot + cn) = make_float2(o.x+v0, o.y+v1);
                } else {
                    *(__half2*)(outh + (size_t)grow*Ntot + cn) = __floats2half2_rn(v0, v1);
                }
            }
        }
    }
}
#define GEMM_SMEM (NSTAGE*ST_H*2)

// ---------------- depthwise 3x3 conv + GELU: smem-tiled ----------------
#define DW_SMEM (6*128*64*2)
__global__ void __launch_bounds__(256) dwconv_gelu(const float* __restrict__ Wdw,
                                                   const float* __restrict__ bdw){
    extern __shared__ __half sh[];
    int blk = blockIdx.x;
    int cg = blk & 15, yt = (blk >> 4) & 31, b = blk >> 9;
    int y0 = yt << 2, c0 = cg << 6;
    int tid = threadIdx.x;

    #pragma unroll
    for(int i = tid; i < 6144; i += 256){
        int r = i >> 10;
        int rem = i & 1023;
        int xx = rem >> 3, seg = (rem & 7) << 3;
        int yy = y0 - 1 + r;
        int4 val = make_int4(0,0,0,0);
        if (yy >= 0 && yy < 128)
            val = *(const int4*)(g_h + ((size_t)((b*128+yy)*128 + xx))*1024 + c0 + seg);
        *(int4*)(sh + ((r*128 + xx) << 6) + seg) = val;
    }
    __syncthreads();

    int ch2 = tid & 31;
    int xs = tid >> 5;
    float wl[9], wh[9];
    #pragma unroll
    for(int t2=0;t2<9;t2++){
        wl[t2] = Wdw[t2*1024 + c0 + 2*ch2];
        wh[t2] = Wdw[t2*1024 + c0 + 2*ch2 + 1];
    }
    float bl = bdw[c0 + 2*ch2], bh = bdw[c0 + 2*ch2 + 1];

    #pragma unroll
    for(int r=0;r<4;r++){
        #pragma unroll
        for(int xi=0;xi<16;xi++){
            int x = xs + (xi << 3);
            float al = bl, ah = bh;
            #pragma unroll
            for(int ky=0;ky<3;ky++){
                int sr = r + ky;
                #pragma unroll
                for(int kx=0;kx<3;kx++){
                    int xx = x + kx - 1;
                    if (xx >= 0 && xx < 128){
                        __half2 hv = *(const __half2*)(sh + ((sr*128 + xx) << 6) + 2*ch2);
                        float2 f = __half22float2(hv);
                        al = fmaf(f.x, wl[ky*3+kx], al);
                        ah = fmaf(f.y, wh[ky*3+kx], ah);
                    }
                }
            }
            float gl = 0.5f*al*(1.f + erff(al*0.70710678118654752f));
            float gh = 0.5f*ah*(1.f + erff(ah*0.70710678118654752f));
            *(__half2*)(g_h2 + ((size_t)((b*128 + y0 + r)*128 + x))*1024 + c0 + 2*ch2)
                = __floats2half2_rn(gl, gh);
        }
    }
}

// ---------------- launch ----------------
extern "C" void kernel_launch(void* const* d_in, const int* in_sizes, int n_in,
                              void* d_out, int out_size){
    const float* x     = (const float*)d_in[0];
    const float* cor   = (const float*)d_in[1];
    const float* g1    = (const float*)d_in[2];
    const float* b1    = (const float*)d_in[3];
    const float* Wq    = (const float*)d_in[4];
    const float* bq    = (const float*)d_in[5];
    const float* Wkv   = (const float*)d_in[6];
    const float* bkv   = (const float*)d_in[7];
    const float* Wproj = (const float*)d_in[8];
    const float* bproj = (const float*)d_in[9];
    const float* Wce   = (const float*)d_in[10];
    const float* bce   = (const float*)d_in[11];
    const float* Wmp   = (const float*)d_in[12];
    const float* bmp   = (const float*)d_in[13];
    const float* g2    = (const float*)d_in[14];
    const float* b2    = (const float*)d_in[15];
    const float* Wfc1  = (const float*)d_in[16];
    const float* bfc1  = (const float*)d_in[17];
    const float* Wdw   = (const float*)d_in[18];
    const float* bdw   = (const float*)d_in[19];
    const float* Wfc2  = (const float*)d_in[20];
    const float* bfc2  = (const float*)d_in[21];

    float* out  = (float*)d_out;
    float* xout = out;
    float* mout = out + (size_t)NTOK*CC;

    __half *p_xn, *p_qkv, *p_att, *p_attce, *p_h, *p_h2, *p_Wqkv, *p_Wp, *p_Wm, *p_W1, *p_W2;
    float *p_bqkv;
    cudaGetSymbolAddress((void**)&p_xn,    g_xn);
    cudaGetSymbolAddress((void**)&p_qkv,   g_qkv);
    cudaGetSymbolAddress((void**)&p_att,   g_att);
    cudaGetSymbolAddress((void**)&p_attce, g_attce);
    cudaGetSymbolAddress((void**)&p_h,     g_h);
    cudaGetSymbolAddress((void**)&p_h2,    g_h2);
    cudaGetSymbolAddress((void**)&p_Wqkv,  g_Wqkv);
    cudaGetSymbolAddress((void**)&p_bqkv,  g_bqkv);
    cudaGetSymbolAddress((void**)&p_Wp,    g_Wp);
    cudaGetSymbolAddress((void**)&p_Wm,    g_Wm);
    cudaGetSymbolAddress((void**)&p_W1,    g_W1);
    cudaGetSymbolAddress((void**)&p_W2,    g_W2);

    cudaFuncSetAttribute(gemm_mma<1>, cudaFuncAttributeMaxDynamicSharedMemorySize, GEMM_SMEM);
    cudaFuncSetAttribute(gemm_mma<2>, cudaFuncAttributeMaxDynamicSharedMemorySize, GEMM_SMEM);
    cudaFuncSetAttribute(gemm_mma<3>, cudaFuncAttributeMaxDynamicSharedMemorySize, GEMM_SMEM);
    cudaFuncSetAttribute(gemm_mma<4>, cudaFuncAttributeMaxDynamicSharedMemorySize, GEMM_SMEM);
    cudaFuncSetAttribute(dwconv_gelu, cudaFuncAttributeMaxDynamicSharedMemorySize, DW_SMEM);
    cudaFuncSetAttribute(attn_kernel, cudaFuncAttributeMaxDynamicSharedMemorySize, ATT_SMEM);

    prep_wqkv<<<768, 256>>>(Wq, bq, Wkv, bkv);
    transpose_h<<<256, 256>>>(Wproj, p_Wp, 256, 256);
    transpose_h<<<64, 256>>>(Wmp, p_Wm, 128, 128);
    transpose_h<<<1024, 256>>>(Wfc1, p_W1, 256, 1024);
    transpose_h<<<1024, 256>>>(Wfc2, p_W2, 1024, 256);

    ln_kernel<true><<<NTOK/8, 256>>>(x, p_xn, g1, b1);
    ce_kernel<<<(NTOK*MD)/256, 256>>>(cor, Wce, bce);
    gemm_mma<4><<<dim3(6, 1024), 256, GEMM_SMEM>>>(p_xn, p_Wqkv, p_bqkv, p_qkv, 256, 768, nullptr);
    attn_kernel<<<NWIN*2, 256, ATT_SMEM>>>();
    gemm_mma<1><<<dim3(2, 1024), 256, GEMM_SMEM>>>(p_att, p_Wp, bproj, xout, 256, 256, p_xn);
    gemm_mma<2><<<dim3(1, 1024), 256, GEMM_SMEM>>>(p_attce, p_Wm, bmp, mout, 128, 128, nullptr);
    ln_kernel<false><<<NTOK/8, 256>>>(xout, p_att, g2, b2);
    gemm_mma<4><<<dim3(8, 1024), 256, GEMM_SMEM>>>(p_att, p_W1, bfc1, p_h, 256, 1024, nullptr);
    dwconv_gelu<<<4096, 256, DW_SMEM>>>(Wdw, bdw);
    gemm_mma<3><<<dim3(2, 1024), 256, GEMM_SMEM>>>(p_h2, p_W2, bfc2, xout, 1024, 256, nullptr);
}

// round 17
// speedup vs baseline: 1.0590x; 1.0528x over previous
#include <cuda_runtime.h>
#include <cuda_fp16.h>
#include <cstdint>
#include <math.h>

#define NWIN 2048
#define TT   64
#define CC   256
#define MD   128
#define HID  1024
#define NTOK (NWIN*TT)   // 131072

// ---------------- scratch ----------------
__device__ __align__(16) __half g_xn[NTOK*CC];
__device__ __align__(16) __half g_qkv[NTOK*768];
__device__ __align__(16) __half g_ce[NTOK*MD];
__device__ __align__(16) __half g_att[NTOK*CC];
__device__ __align__(16) __half g_attce[NTOK*MD];
__device__ __align__(16) __half g_h[NTOK*HID];
__device__ __align__(16) __half g_h2[NTOK*HID];
__device__ __align__(16) __half g_Wqkv[768*256];    // [N][K]
__device__ __align__(16) float  g_bqkv[768];
__device__ __align__(16) __half g_Wp[256*256];      // [N][K]
__device__ __align__(16) __half g_Wm[128*128];
__device__ __align__(16) __half g_W1[1024*256];
__device__ __align__(16) __half g_W2[256*1024];

__device__ __forceinline__ int win2glob(int row){
    int w = row >> 6, t = row & 63;
    int b = w >> 8, wi = w & 255;
    int gy = ((wi >> 4) << 3) + (t >> 3);
    int gx = ((wi & 15) << 3) + (t & 7);
    return (b*128 + gy)*128 + gx;
}

__device__ __forceinline__ void mma_f16(float* c, const uint32_t* a, const uint32_t* b){
    asm volatile("mma.sync.aligned.m16n8k16.row.col.f32.f16.f16.f32 "
        "{%0,%1,%2,%3}, {%4,%5,%6,%7}, {%8,%9}, {%0,%1,%2,%3};"
        : "+f"(c[0]), "+f"(c[1]), "+f"(c[2]), "+f"(c[3])
        : "r"(a[0]), "r"(a[1]), "r"(a[2]), "r"(a[3]), "r"(b[0]), "r"(b[1]));
}
__device__ __forceinline__ uint32_t smem_u32(const void* p){
    uint32_t a;
    asm("{ .reg .u64 t; cvta.to.shared.u64 t, %1; cvt.u32.u64 %0, t; }" : "=r"(a) : "l"(p));
    return a;
}
__device__ __forceinline__ void cpasync16(uint32_t dst, const void* src){
    asm volatile("cp.async.ca.shared.global [%0], [%1], 16;" :: "r"(dst), "l"(src));
}
#define CP_COMMIT() asm volatile("cp.async.commit_group;" ::: "memory")
__device__ __forceinline__ uint32_t f2h2(float a, float b){
    __half2 h = __floats2half2_rn(a, b);
    return *(uint32_t*)&h;
}
__device__ __forceinline__ void ldm_x4(uint32_t* r, uint32_t addr){
    asm volatile("ldmatrix.sync.aligned.m8n8.x4.shared.b16 {%0,%1,%2,%3}, [%4];"
        : "=r"(r[0]), "=r"(r[1]), "=r"(r[2]), "=r"(r[3]) : "r"(addr));
}

// ---------------- weight prep: transpose+fp16 ----------------
__global__ void prep_wqkv(const float* __restrict__ Wq, const float* __restrict__ bq,
                          const float* __restrict__ Wkv, const float* __restrict__ bkv){
    int i = blockIdx.x*blockDim.x + threadIdx.x;   // 768*256
    int n = i >> 8, k = i & 255;
    float v = (n < 256) ? Wq[k*256 + n] : Wkv[k*512 + (n - 256)];
    g_Wqkv[i] = __float2half_rn(v);
    if (i < 768) g_bqkv[i] = (i < 256) ? bq[i] : bkv[i - 256];
}
__global__ void transpose_h(const float* __restrict__ in, __half* __restrict__ out, int K, int N){
    int i = blockIdx.x*blockDim.x + threadIdx.x;   // N*K
    int n = i / K, k = i % K;
    out[i] = __float2half_rn(in[(size_t)k*N + n]);
}

// ---------------- LayerNorm (fp16 output) ----------------
template<bool GATHER>
__global__ void ln_kernel(const float* __restrict__ x, __half* __restrict__ out,
                          const float* __restrict__ gg, const float* __restrict__ bb){
    int row  = blockIdx.x*8 + (threadIdx.x >> 5);
    int lane = threadIdx.x & 31;
    const float* src = x + (size_t)(GATHER ? win2glob(row) : row)*CC;
    float v[8]; float s = 0.f;
    #pragma unroll
    for(int i=0;i<8;i++){ v[i] = src[lane + i*32]; s += v[i]; }
    #pragma unroll
    for(int o=16;o;o>>=1) s += __shfl_xor_sync(0xffffffffu, s, o);
    float mean = s * (1.f/CC);
    float s2 = 0.f;
    #pragma unroll
    for(int i=0;i<8;i++){ float d = v[i]-mean; s2 += d*d; }
    #pragma unroll
    for(int o=16;o;o>>=1) s2 += __shfl_xor_sync(0xffffffffu, s2, o);
    float rstd = rsqrtf(s2*(1.f/CC) + 1e-5f);
    __half* dst = out + (size_t)row*CC;
    #pragma unroll
    for(int i=0;i<8;i++){
        int c = lane + i*32;
        dst[c] = __float2half_rn((v[i]-mean)*rstd*gg[c] + bb[c]);
    }
}

// ---------------- coordinate embedding (fp16 out) ----------------
__global__ void ce_kernel(const float* __restrict__ cor, const float* __restrict__ Wce,
                          const float* __restrict__ bce){
    int i = blockIdx.x*blockDim.x + threadIdx.x;
    int row = i >> 7, m = i & 127;
    int gp = win2glob(row)*2;
    g_ce[i] = __float2half_rn(cor[gp]*Wce[m] + cor[gp+1]*Wce[MD+m] + bce[m]);
}

// ---------------- attention: tensor-core (FA2-style), fp16 in/out ----------------
#define QP 136
#define CP 72
#define ATT_SMEM ((3*64*QP + 64*CP)*2)
__global__ void __launch_bounds__(256) attn_kernel(){
    extern __shared__ __half sm_att[];
    __half* Qs = sm_att;             // [64][136]
    __half* Ks = Qs + 64*QP;
    __half* Vs = Ks + 64*QP;
    __half* Cs = Vs + 64*QP;         // [64][72]

    int blk = blockIdx.x;            // 4096
    int w = blk >> 1, hh = blk & 1;
    int pw = (w + 1024) & 2047;
    int tid = threadIdx.x;
    int wid = tid >> 5, lane = tid & 31;
    int ch = wid >> 1;               // local head 0..3
    int qh = wid & 1;                // query half
    int g = lane >> 2, tg = lane & 3;

    for(int i=tid; i<1024; i+=256){
        int r = i >> 4, seg = (i & 15) << 3;
        const __half* bq_ = g_qkv + (size_t)(w*64 + r)*768 + hh*128;
        const __half* bk_ = g_qkv + (size_t)(pw*64 + r)*768 + 256 + hh*128;
        const __half* bv_ = g_qkv + (size_t)(pw*64 + r)*768 + 512 + hh*128;
        *(int4*)&Qs[r*QP + seg] = *(const int4*)(bq_ + seg);
        *(int4*)&Ks[r*QP + seg] = *(const int4*)(bk_ + seg);
        *(int4*)&Vs[r*QP + seg] = *(const int4*)(bv_ + seg);
    }
    for(int i=tid; i<512; i+=256){
        int r = i >> 3, seg = (i & 7) << 3;
        *(int4*)&Cs[r*CP + seg] = *(const int4*)(g_ce + (size_t)(w*64 + r)*128 + hh*64 + seg);
    }
    __syncthreads();

    int c0 = ch*32;
    int lr = lane & 7;
    int ts4 = lane >> 3;
    int ts2 = ts4 & 1;

    uint32_t qf[2][2][4];
    #pragma unroll
    for(int mt=0; mt<2; mt++){
        #pragma unroll
        for(int kc=0; kc<2; kc++){
            int row = qh*32 + mt*16 + lr + ((ts4 & 1) << 3);
            int col = c0 + kc*16 + ((ts4 & 2) << 2);
            uint32_t addr = smem_u32(&Qs[row*QP + col]);
            asm volatile("ldmatrix.sync.aligned.m8n8.x4.shared.b16 {%0,%1,%2,%3}, [%4];"
                : "=r"(qf[mt][kc][0]), "=r"(qf[mt][kc][1]),
                  "=r"(qf[mt][kc][2]), "=r"(qf[mt][kc][3]) : "r"(addr));
        }
    }

    float S[2][8][4];
    #pragma unroll
    for(int mt=0;mt<2;mt++)
        #pragma unroll
        for(int nt=0;nt<8;nt++)
            #pragma unroll
            for(int i=0;i<4;i++) S[mt][nt][i] = 0.f;

    #pragma unroll
    for(int kc=0; kc<2; kc++){
        #pragma unroll
        for(int nt=0; nt<8; nt++){
            uint32_t bb[2];
            uint32_t addr = smem_u32(&Ks[(nt*8 + lr)*QP + c0 + kc*16 + ts2*8]);
            asm volatile("ldmatrix.sync.aligned.m8n8.x2.shared.b16 {%0,%1}, [%2];"
                : "=r"(bb[0]), "=r"(bb[1]) : "r"(addr));
            mma_f16(S[0][nt], qf[0][kc], bb);
            mma_f16(S[1][nt], qf[1][kc], bb);
        }
    }

    const float sc = 0.17677669529663687f;
    float inv[2][2];
    #pragma unroll
    for(int mt=0;mt<2;mt++){
        #pragma unroll
        for(int rh=0;rh<2;rh++){
            float m = -1e30f;
            #pragma unroll
            for(int nt=0;nt<8;nt++){
                m = fmaxf(m, S[mt][nt][rh*2]);
                m = fmaxf(m, S[mt][nt][rh*2+1]);
            }
            m = fmaxf(m, __shfl_xor_sync(0xffffffffu, m, 1));
            m = fmaxf(m, __shfl_xor_sync(0xffffffffu, m, 2));
            float sm_ = 0.f;
            #pragma unroll
            for(int nt=0;nt<8;nt++){
                float p0 = expf(sc*(S[mt][nt][rh*2]   - m));
                float p1 = expf(sc*(S[mt][nt][rh*2+1] - m));
                S[mt][nt][rh*2] = p0; S[mt][nt][rh*2+1] = p1;
                sm_ += p0 + p1;
            }
            sm_ += __shfl_xor_sync(0xffffffffu, sm_, 1);
            sm_ += __shfl_xor_sync(0xffffffffu, sm_, 2);
            inv[mt][rh] = 1.f/sm_;
        }
    }

    float AV[2][4][4], AC[2][2][4];
    #pragma unroll
    for(int mt=0;mt<2;mt++){
        #pragma unroll
        for(int dn=0;dn<4;dn++)
            #pragma unroll
            for(int i=0;i<4;i++) AV[mt][dn][i] = 0.f;
        #pragma unroll
        for(int dn=0;dn<2;dn++)
            #pragma unroll
            for(int i=0;i<4;i++) AC[mt][dn][i] = 0.f;
    }

    #pragma unroll
    for(int kc2=0; kc2<4; kc2++){
        uint32_t pf[2][4];
        #pragma unroll
        for(int mt=0;mt<2;mt++){
            pf[mt][0] = f2h2(S[mt][2*kc2][0],   S[mt][2*kc2][1]);
            pf[mt][1] = f2h2(S[mt][2*kc2][2],   S[mt][2*kc2][3]);
            pf[mt][2] = f2h2(S[mt][2*kc2+1][0], S[mt][2*kc2+1][1]);
            pf[mt][3] = f2h2(S[mt][2*kc2+1][2], S[mt][2*kc2+1][3]);
        }
        #pragma unroll
        for(int dn=0; dn<4; dn++){
            uint32_t bb[2];
            uint32_t addr = smem_u32(&Vs[(kc2*16 + ts2*8 + lr)*QP + c0 + dn*8]);
            asm volatile("ldmatrix.sync.aligned.m8n8.x2.trans.shared.b16 {%0,%1}, [%2];"
                : "=r"(bb[0]), "=r"(bb[1]) : "r"(addr));
            mma_f16(AV[0][dn], pf[0], bb);
            mma_f16(AV[1][dn], pf[1], bb);
        }
        #pragma unroll
        for(int dn=0; dn<2; dn++){
            uint32_t bb[2];
            uint32_t addr = smem_u32(&Cs[(kc2*16 + ts2*8 + lr)*CP + ch*16 + dn*8]);
            asm volatile("ldmatrix.sync.aligned.m8n8.x2.trans.shared.b16 {%0,%1}, [%2];"
                : "=r"(bb[0]), "=r"(bb[1]) : "r"(addr));
            mma_f16(AC[0][dn], pf[0], bb);
            mma_f16(AC[1][dn], pf[1], bb);
        }
    }

    #pragma unroll
    for(int mt=0;mt<2;mt++){
        #pragma unroll
        for(int rh=0;rh<2;rh++){
            int lrow = qh*32 + mt*16 + g + rh*8;
            int grow = w*64 + lrow;
            float iv = inv[mt][rh];
            __half* ao = g_att + (size_t)grow*256 + hh*128 + c0;
            #pragma unroll
            for(int dn=0;dn<4;dn++)
                *(__half2*)(ao + dn*8 + 2*tg) =
                    __floats2half2_rn(AV[mt][dn][rh*2]*iv, AV[mt][dn][rh*2+1]*iv);
            __half* co = g_attce + (size_t)grow*128 + hh*64 + ch*16;
            #pragma unroll
            for(int dn=0;dn<2;dn++){
                __half2 cv = *(__half2*)&Cs[lrow*CP + ch*16 + dn*8 + 2*tg];
                float2 cf = __half22float2(cv);
                *(__half2*)(co + dn*8 + 2*tg) =
                    __floats2half2_rn(AC[mt][dn][rh*2]*iv - cf.x,
                                      AC[mt][dn][rh*2+1]*iv - cf.y);
            }
        }
    }
}

// ---------------- FP16 mma.sync GEMM: 128x128 block, chunk K=64, 4-stage, ldmatrix ----------------
// MODE 0: store fp32; 1: scatter+residual(half)->fp32; 2: scatter fp32;
// MODE 3: fp32 out += val; 4: store fp16
#define KCH 64
#define PITCHH 72
#define AS_H (128*PITCHH)
#define ST_H (2*AS_H)
#define NSTAGE 4

template<int MODE>
__global__ void __launch_bounds__(256) gemm_mma(const __half* __restrict__ A,
        const __half* __restrict__ Wt, const float* __restrict__ bias,
        void* __restrict__ outv, int K, int Ntot, const __half* __restrict__ add){
    extern __shared__ __half smh[];

    int tid = threadIdx.x;
    int wid = tid >> 5, lane = tid & 31;
    int g = lane >> 2, tg = lane & 3;
    int bm = blockIdx.y << 7, bn = blockIdx.x << 7;
    int mBase = (wid & 3) << 5;
    int nBase = (wid >> 2) << 6;

    float c[2][8][4];
    #pragma unroll
    for(int i=0;i<2;i++)
        #pragma unroll
        for(int j=0;j<8;j++)
            #pragma unroll
            for(int q=0;q<4;q++) c[i][j][q] = 0.f;

    int nch = K / KCH;
    uint32_t smB = smem_u32(smh);

    // ldmatrix per-lane row/col offsets (within tile, in halves)
    int aRowL = mBase + (lane & 15);
    int aColL = (lane >> 4) << 3;
    int bRowL = nBase + ((lane >> 4) << 3) + (lane & 7);
    int bColL = ((lane >> 3) & 1) << 3;

    auto issue = [&](int ch){
        uint32_t st = smB + (uint32_t)((ch % NSTAGE) * ST_H) * 2u;
        int k0 = ch * KCH;
        #pragma unroll
        for(int i=0;i<4;i++){
            int idx = i*256 + tid;
            int row = idx >> 3, seg = (idx & 7) << 3;
            cpasync16(st + (uint32_t)(row*PITCHH + seg)*2u,
                      A + (size_t)(bm + row)*K + k0 + seg);
            cpasync16(st + (uint32_t)(AS_H + row*PITCHH + seg)*2u,
                      Wt + (size_t)(bn + row)*K + k0 + seg);
        }
        CP_COMMIT();
    };

    issue(0);
    if (nch > 1) issue(1); else CP_COMMIT();
    if (nch > 2) issue(2); else CP_COMMIT();

    for(int ch=0; ch<nch; ch++){
        asm volatile("cp.async.wait_group 2;" ::: "memory");
        __syncthreads();
        if (ch + 3 < nch) issue(ch + 3);
        else CP_COMMIT();

        const __half* Ah = smh + (size_t)(ch % NSTAGE) * ST_H;
        const __half* Bh = Ah + AS_H;

        uint32_t afA[2][4], bfA[8][2], afB[2][4], bfB[8][2];

        #define LOAD_FRAGS(kk, af, bf) do{                                        \
            _Pragma("unroll")                                                     \
            for(int mt=0; mt<2; mt++)                                             \
                ldm_x4(af[mt], smem_u32(&Ah[(aRowL + mt*16)*PITCHH + (kk) + aColL])); \
            _Pragma("unroll")                                                     \
            for(int jp=0; jp<4; jp++){                                            \
                uint32_t rr[4];                                                   \
                ldm_x4(rr, smem_u32(&Bh[(bRowL + jp*16)*PITCHH + (kk) + bColL])); \
                bf[2*jp][0]   = rr[0]; bf[2*jp][1]   = rr[1];                     \
                bf[2*jp+1][0] = rr[2]; bf[2*jp+1][1] = rr[3];                     \
            } }while(0)

        #define DO_MMA(af, bf) do{                                       \
            _Pragma("unroll")                                            \
            for(int mt=0; mt<2; mt++)                                    \
                _Pragma("unroll")                                        \
                for(int j=0; j<8; j++)                                   \
                    mma_f16(c[mt][j], af[mt], bf[j]);                    \
            }while(0)

        LOAD_FRAGS(0, afA, bfA);
        LOAD_FRAGS(16, afB, bfB);  DO_MMA(afA, bfA);
        LOAD_FRAGS(32, afA, bfA);  DO_MMA(afB, bfB);
        LOAD_FRAGS(48, afB, bfB);  DO_MMA(afA, bfA);
        DO_MMA(afB, bfB);

        #undef LOAD_FRAGS
        #undef DO_MMA
    }

    float* outf = (float*)outv;
    __half* outh = (__half*)outv;
    #pragma unroll
    for(int mt=0; mt<2; mt++){
        #pragma unroll
        for(int half=0; half<2; half++){
            int grow = bm + mBase + (mt<<4) + g + (half<<3);
            int orow = (MODE==1 || MODE==2) ? win2glob(grow) : grow;
            #pragma unroll
            for(int j=0; j<8; j++){
                int cn = bn + nBase + (j<<3) + (tg<<1);
                float2 bb = *(const float2*)(bias + cn);
                float v0 = c[mt][j][half*2+0] + bb.x;
                float v1 = c[mt][j][half*2+1] + bb.y;
                if (MODE == 0){
                    *(float2*)(outf + (size_t)grow*Ntot + cn) = make_float2(v0, v1);
                } else if (MODE == 1){
                    __half2 ad = *(const __half2*)(add + (size_t)grow*Ntot + cn);
                    *(float2*)(outf + (size_t)orow*Ntot + cn) =
                        make_float2(v0 + __half2float(ad.x), v1 + __half2float(ad.y));
                } else if (MODE == 2){
                    *(float2*)(outf + (size_t)orow*Ntot + cn) = make_float2(v0, v1);
                } else if (MODE == 3){
                    float2 o = *(float2*)(outf + (size_t)grow*Ntot + cn);
                    *(float2*)(outf + (size_t)grow*Ntot + cn) = make_float2(o.x+v0, o.y+v1);
                } else {
                    *(__half2*)(outh + (size_t)grow*Ntot + cn) = __floats2half2_rn(v0, v1);
                }
            }
        }
    }
}
#define GEMM_SMEM (NSTAGE*ST_H*2)

// ---------------- depthwise 3x3 conv + GELU: smem-tiled ----------------
#define DW_SMEM (6*128*64*2)
__global__ void __launch_bounds__(256) dwconv_gelu(const float* __restrict__ Wdw,
                                                   const float* __restrict__ bdw){
    extern __shared__ __half sh[];
    int blk = blockIdx.x;
    int cg = blk & 15, yt = (blk >> 4) & 31, b = blk >> 9;
    int y0 = yt << 2, c0 = cg << 6;
    int tid = threadIdx.x;

    #pragma unroll
    for(int i = tid; i < 6144; i += 256){
        int r = i >> 10;
        int rem = i & 1023;
        int xx = rem >> 3, seg = (rem & 7) << 3;
        int yy = y0 - 1 + r;
        int4 val = make_int4(0,0,0,0);
        if (yy >= 0 && yy < 128)
            val = *(const int4*)(g_h + ((size_t)((b*128+yy)*128 + xx))*1024 + c0 + seg);
        *(int4*)(sh + ((r*128 + xx) << 6) + seg) = val;
    }
    __syncthreads();

    int ch2 = tid & 31;
    int xs = tid >> 5;
    float wl[9], wh[9];
    #pragma unroll
    for(int t2=0;t2<9;t2++){
        wl[t2] = Wdw[t2*1024 + c0 + 2*ch2];
        wh[t2] = Wdw[t2*1024 + c0 + 2*ch2 + 1];
    }
    float bl = bdw[c0 + 2*ch2], bh = bdw[c0 + 2*ch2 + 1];

    #pragma unroll
    for(int r=0;r<4;r++){
        #pragma unroll
        for(int xi=0;xi<16;xi++){
            int x = xs + (xi << 3);
            float al = bl, ah = bh;
            #pragma unroll
            for(int ky=0;ky<3;ky++){
                int sr = r + ky;
                #pragma unroll
                for(int kx=0;kx<3;kx++){
                    int xx = x + kx - 1;
                    if (xx >= 0 && xx < 128){
                        __half2 hv = *(const __half2*)(sh + ((sr*128 + xx) << 6) + 2*ch2);
                        float2 f = __half22float2(hv);
                        al = fmaf(f.x, wl[ky*3+kx], al);
                        ah = fmaf(f.y, wh[ky*3+kx], ah);
                    }
                }
            }
            float gl = 0.5f*al*(1.f + erff(al*0.70710678118654752f));
            float gh = 0.5f*ah*(1.f + erff(ah*0.70710678118654752f));
            *(__half2*)(g_h2 + ((size_t)((b*128 + y0 + r)*128 + x))*1024 + c0 + 2*ch2)
                = __floats2half2_rn(gl, gh);
        }
    }
}

// ---------------- launch ----------------
extern "C" void kernel_launch(void* const* d_in, const int* in_sizes, int n_in,
                              void* d_out, int out_size){
    const float* x     = (const float*)d_in[0];
    const float* cor   = (const float*)d_in[1];
    const float* g1    = (const float*)d_in[2];
    const float* b1    = (const float*)d_in[3];
    const float* Wq    = (const float*)d_in[4];
    const float* bq    = (const float*)d_in[5];
    const float* Wkv   = (const float*)d_in[6];
    const float* bkv   = (const float*)d_in[7];
    const float* Wproj = (const float*)d_in[8];
    const float* bproj = (const float*)d_in[9];
    const float* Wce   = (const float*)d_in[10];
    const float* bce   = (const float*)d_in[11];
    const float* Wmp   = (const float*)d_in[12];
    const float* bmp   = (const float*)d_in[13];
    const float* g2    = (const float*)d_in[14];
    const float* b2    = (const float*)d_in[15];
    const float* Wfc1  = (const float*)d_in[16];
    const float* bfc1  = (const float*)d_in[17];
    const float* Wdw   = (const float*)d_in[18];
    const float* bdw   = (const float*)d_in[19];
    const float* Wfc2  = (const float*)d_in[20];
    const float* bfc2  = (const float*)d_in[21];

    float* out  = (float*)d_out;
    float* xout = out;
    float* mout = out + (size_t)NTOK*CC;

    __half *p_xn, *p_qkv, *p_att, *p_attce, *p_h, *p_h2, *p_Wqkv, *p_Wp, *p_Wm, *p_W1, *p_W2;
    float *p_bqkv;
    cudaGetSymbolAddress((void**)&p_xn,    g_xn);
    cudaGetSymbolAddress((void**)&p_qkv,   g_qkv);
    cudaGetSymbolAddress((void**)&p_att,   g_att);
    cudaGetSymbolAddress((void**)&p_attce, g_attce);
    cudaGetSymbolAddress((void**)&p_h,     g_h);
    cudaGetSymbolAddress((void**)&p_h2,    g_h2);
    cudaGetSymbolAddress((void**)&p_Wqkv,  g_Wqkv);
    cudaGetSymbolAddress((void**)&p_bqkv,  g_bqkv);
    cudaGetSymbolAddress((void**)&p_Wp,    g_Wp);
    cudaGetSymbolAddress((void**)&p_Wm,    g_Wm);
    cudaGetSymbolAddress((void**)&p_W1,    g_W1);
    cudaGetSymbolAddress((void**)&p_W2,    g_W2);

    cudaFuncSetAttribute(gemm_mma<1>, cudaFuncAttributeMaxDynamicSharedMemorySize, GEMM_SMEM);
    cudaFuncSetAttribute(gemm_mma<2>, cudaFuncAttributeMaxDynamicSharedMemorySize, GEMM_SMEM);
    cudaFuncSetAttribute(gemm_mma<3>, cudaFuncAttributeMaxDynamicSharedMemorySize, GEMM_SMEM);
    cudaFuncSetAttribute(gemm_mma<4>, cudaFuncAttributeMaxDynamicSharedMemorySize, GEMM_SMEM);
    cudaFuncSetAttribute(dwconv_gelu, cudaFuncAttributeMaxDynamicSharedMemorySize, DW_SMEM);
    cudaFuncSetAttribute(attn_kernel, cudaFuncAttributeMaxDynamicSharedMemorySize, ATT_SMEM);

    prep_wqkv<<<768, 256>>>(Wq, bq, Wkv, bkv);
    transpose_h<<<256, 256>>>(Wproj, p_Wp, 256, 256);
    transpose_h<<<64, 256>>>(Wmp, p_Wm, 128, 128);
    transpose_h<<<1024, 256>>>(Wfc1, p_W1, 256, 1024);
    transpose_h<<<1024, 256>>>(Wfc2, p_W2, 1024, 256);

    ln_kernel<true><<<NTOK/8, 256>>>(x, p_xn, g1, b1);
    ce_kernel<<<(NTOK*MD)/256, 256>>>(cor, Wce, bce);
    gemm_mma<4><<<dim3(6, 1024), 256, GEMM_SMEM>>>(p_xn, p_Wqkv, p_bqkv, p_qkv, 256, 768, nullptr);
    attn_kernel<<<NWIN*2, 256, ATT_SMEM>>>();
    gemm_mma<1><<<dim3(2, 1024), 256, GEMM_SMEM>>>(p_att, p_Wp, bproj, xout, 256, 256, p_xn);
    gemm_mma<2><<<dim3(1, 1024), 256, GEMM_SMEM>>>(p_attce, p_Wm, bmp, mout, 128, 128, nullptr);
    ln_kernel<false><<<NTOK/8, 256>>>(xout, p_att, g2, b2);
    gemm_mma<4><<<dim3(8, 1024), 256, GEMM_SMEM>>>(p_att, p_W1, bfc1, p_h, 256, 1024, nullptr);
    dwconv_gelu<<<4096, 256, DW_SMEM>>>(Wdw, bdw);
    gemm_mma<3><<<dim3(2, 1024), 256, GEMM_SMEM>>>(p_h2, p_W2, bfc2, xout, 1024, 256, nullptr);
}